// round 7
// baseline (speedup 1.0000x reference)
#include <cuda_runtime.h>
#include <math.h>

#define T_STEPS 4096
#define NC 4880
#define VD 512
#define HD 512
#define G3 1536
#define NB 64     // scan blocks: 64 x 8 warps = 512 outputs
#define NBP 64    // attention partial blocks

// ---------------- scratch (device globals; no allocation) ----------------
__device__ float d_visit[T_STEPS * VD];      // 8 MB
__device__ float d_gi[T_STEPS * G3];         // 24 MB
__device__ float d_hs[T_STEPS * HD];         // 8 MB
__device__ __align__(16) float d_hbuf[2][HD];
__device__ __align__(8) unsigned d_done[NB]; // per-block epoch counters
__device__ float d_logits[T_STEPS];
__device__ float d_alpha[T_STEPS];
__device__ float d_part[NBP * HD];

// ---------------- helpers ----------------
__device__ __forceinline__ unsigned long long ld_acq64(const unsigned* p) {
    unsigned long long v;
    asm volatile("ld.acquire.gpu.u64 %0, [%1];" : "=l"(v) : "l"(p) : "memory");
    return v;
}
__device__ __forceinline__ void st_rel(unsigned* p, unsigned v) {
    asm volatile("st.release.gpu.u32 [%0], %1;" :: "l"(p), "r"(v) : "memory");
}
__device__ __forceinline__ float4 ldcg_v4(const float* p) {
    float4 v;
    asm volatile("ld.global.cg.v4.f32 {%0,%1,%2,%3}, [%4];"
                 : "=f"(v.x), "=f"(v.y), "=f"(v.z), "=f"(v.w) : "l"(p) : "memory");
    return v;
}
__device__ __forceinline__ void stcg_f32(float* p, float a) {
    asm volatile("st.global.cg.f32 [%0], %1;" :: "l"(p), "f"(a) : "memory");
}
__device__ __forceinline__ float fast_sigmoid(float x) {
    // 1/(1+e^-x); saturates correctly: e^-x -> inf => 0 ; -> 0 => 1
    return __fdividef(1.f, 1.f + __expf(-x));
}
__device__ __forceinline__ float fast_tanh(float x) {
    // 1 - 2/(e^{2x}+1); x->+inf: 1-0=1 ; x->-inf: 1-2=-1
    return 1.f - __fdividef(2.f, __expf(2.f * x) + 1.f);
}

// ============================================================
// GEMM1: d_visit[t][d] = sum_c H[c][t] * X[c][d]
// Both K(=c)-major. 128x128 tile, BK=8, 256 threads, 8x8 per thread.
// ============================================================
__global__ __launch_bounds__(256) void gemm1_kernel(const float* __restrict__ Hm,
                                                    const float* __restrict__ Xe) {
    __shared__ __align__(16) float As[8][128];
    __shared__ __align__(16) float Bs[8][128];
    const int t0 = blockIdx.x * 128;
    const int d0 = blockIdx.y * 128;
    const int tid = threadIdx.x;
    const int kk = tid >> 5;
    const int c4 = (tid & 31) << 2;
    const int ty = (tid >> 4) << 3;
    const int tx = (tid & 15) << 3;

    float acc[8][8];
#pragma unroll
    for (int i = 0; i < 8; i++)
#pragma unroll
        for (int j = 0; j < 8; j++) acc[i][j] = 0.f;

    for (int c0 = 0; c0 < NC; c0 += 8) {
        *(float4*)&As[kk][c4] = *(const float4*)&Hm[(size_t)(c0 + kk) * T_STEPS + t0 + c4];
        *(float4*)&Bs[kk][c4] = *(const float4*)&Xe[(size_t)(c0 + kk) * VD + d0 + c4];
        __syncthreads();
#pragma unroll
        for (int k = 0; k < 8; k++) {
            float a[8], b[8];
            *(float4*)&a[0] = *(float4*)&As[k][ty];
            *(float4*)&a[4] = *(float4*)&As[k][ty + 4];
            *(float4*)&b[0] = *(float4*)&Bs[k][tx];
            *(float4*)&b[4] = *(float4*)&Bs[k][tx + 4];
#pragma unroll
            for (int i = 0; i < 8; i++)
#pragma unroll
                for (int j = 0; j < 8; j++) acc[i][j] = fmaf(a[i], b[j], acc[i][j]);
        }
        __syncthreads();
    }
#pragma unroll
    for (int i = 0; i < 8; i++)
#pragma unroll
        for (int j = 0; j < 8; j += 4) {
            float4 v = make_float4(acc[i][j], acc[i][j + 1], acc[i][j + 2], acc[i][j + 3]);
            *(float4*)&d_visit[(size_t)(t0 + ty + i) * VD + d0 + tx + j] = v;
        }
}

// ============================================================
// GEMM2: d_gi[t][g] = sum_k d_visit[t][k] * W_ih[g][k] + b_ih[g]
// ============================================================
__global__ __launch_bounds__(256) void gemm2_kernel(const float* __restrict__ Wih,
                                                    const float* __restrict__ bih) {
    __shared__ __align__(16) float As[8][132];
    __shared__ __align__(16) float Bs[8][132];
    const int t0 = blockIdx.x * 128;
    const int g0 = blockIdx.y * 128;
    const int tid = threadIdx.x;
    const int row = tid >> 1;
    const int kc = (tid & 1) << 2;
    const int ty = (tid >> 4) << 3;
    const int tx = (tid & 15) << 3;

    float acc[8][8];
#pragma unroll
    for (int i = 0; i < 8; i++)
#pragma unroll
        for (int j = 0; j < 8; j++) acc[i][j] = 0.f;

    for (int k0 = 0; k0 < VD; k0 += 8) {
        float4 av = *(const float4*)&d_visit[(size_t)(t0 + row) * VD + k0 + kc];
        float4 bv = *(const float4*)&Wih[(size_t)(g0 + row) * VD + k0 + kc];
        As[kc + 0][row] = av.x; As[kc + 1][row] = av.y;
        As[kc + 2][row] = av.z; As[kc + 3][row] = av.w;
        Bs[kc + 0][row] = bv.x; Bs[kc + 1][row] = bv.y;
        Bs[kc + 2][row] = bv.z; Bs[kc + 3][row] = bv.w;
        __syncthreads();
#pragma unroll
        for (int k = 0; k < 8; k++) {
            float a[8], b[8];
            *(float4*)&a[0] = *(float4*)&As[k][ty];
            *(float4*)&a[4] = *(float4*)&As[k][ty + 4];
            *(float4*)&b[0] = *(float4*)&Bs[k][tx];
            *(float4*)&b[4] = *(float4*)&Bs[k][tx + 4];
#pragma unroll
            for (int i = 0; i < 8; i++)
#pragma unroll
                for (int j = 0; j < 8; j++) acc[i][j] = fmaf(a[i], b[j], acc[i][j]);
        }
        __syncthreads();
    }
#pragma unroll
    for (int i = 0; i < 8; i++)
#pragma unroll
        for (int j = 0; j < 8; j++) {
            d_gi[(size_t)(t0 + ty + i) * G3 + g0 + tx + j] = acc[i][j] + bih[g0 + tx + j];
        }
}

// ============================================================
// init: zero h0 buffer + reset epoch counters (graph-replay safe)
// ============================================================
__global__ void init_kernel() {
    const int j = threadIdx.x;               // 0..511
    d_hbuf[0][j] = 0.f;
    if (j < NB) d_done[j] = 0u;
}

// ============================================================
// GRU scan: 64 blocks x 256 threads; warp w owns output j = blk*8+w.
// W_hh rows {j, j+512, j+1024} live in registers (48 floats/lane).
// Sync: decentralized epoch counters d_done[64]; each block publishes
// (threadfence + release store) after storing its h slice; every warp
// polls all 64 counters (2 per lane via one 64-bit acquire load).
// ============================================================
__global__ __launch_bounds__(256) void gru_scan_kernel(const float* __restrict__ Whh,
                                                       const float* __restrict__ bhh) {
    const int tid = threadIdx.x;
    const int w = tid >> 5;
    const int l = tid & 31;
    const int j = blockIdx.x * 8 + w;     // output index < 512

    // --- preload W_hh rows into registers; lane l covers cols c = 4*(l+32q) ---
    float4 wr[4], wz[4], wn[4];
#pragma unroll
    for (int q = 0; q < 4; q++) {
        const int c = 4 * (l + 32 * q);
        wr[q] = *(const float4*)&Whh[(size_t)j * HD + c];
        wz[q] = *(const float4*)&Whh[(size_t)(j + 512) * HD + c];
        wn[q] = *(const float4*)&Whh[(size_t)(j + 1024) * HD + c];
    }
    const float br = bhh[j];
    const float bz = bhh[j + 512];
    const float bn = bhh[j + 1024];

    // gi for t=0 prefetched
    float gr = d_gi[j], gz = d_gi[j + 512], gn = d_gi[j + 1024];
    float hprev = 0.f;

    const unsigned* mydone = &d_done[l * 2];   // lane l watches counters 2l, 2l+1

    for (int t = 0; t < T_STEPS; t++) {
        // --- wait until every block has published state t ---
        if (t > 0) {
            const unsigned want = (unsigned)t;
            int guard = 0;
            bool ok;
            do {
                unsigned long long v = ld_acq64(mydone);
                ok = ((unsigned)v >= want) & ((unsigned)(v >> 32) >= want);
            } while (!__all_sync(0xffffffffu, ok) && ++guard < (1 << 20));
        }

        // --- load h state t (L2-fresh) ---
        float4 hv[4];
#pragma unroll
        for (int q = 0; q < 4; q++) hv[q] = ldcg_v4(&d_hbuf[t & 1][4 * (l + 32 * q)]);

        // prefetch gi for t+1 (broadcast loads, off the critical path)
        float gr2 = 0.f, gz2 = 0.f, gn2 = 0.f;
        if (t + 1 < T_STEPS) {
            const float* gp = d_gi + (size_t)(t + 1) * G3 + j;
            gr2 = __ldg(gp); gz2 = __ldg(gp + 512); gn2 = __ldg(gp + 1024);
        }

        // --- three partial dots from registers ---
        float ar = 0.f, az = 0.f, an = 0.f;
#pragma unroll
        for (int q = 0; q < 4; q++) {
            float4 h = hv[q];
            ar = fmaf(wr[q].x, h.x, fmaf(wr[q].y, h.y, fmaf(wr[q].z, h.z, fmaf(wr[q].w, h.w, ar))));
            az = fmaf(wz[q].x, h.x, fmaf(wz[q].y, h.y, fmaf(wz[q].z, h.z, fmaf(wz[q].w, h.w, az))));
            an = fmaf(wn[q].x, h.x, fmaf(wn[q].y, h.y, fmaf(wn[q].z, h.z, fmaf(wn[q].w, h.w, an))));
        }
#pragma unroll
        for (int off = 16; off; off >>= 1) {
            ar += __shfl_xor_sync(0xffffffffu, ar, off);
            az += __shfl_xor_sync(0xffffffffu, az, off);
            an += __shfl_xor_sync(0xffffffffu, an, off);
        }

        float r = fast_sigmoid(gr + ar + br);
        float z = fast_sigmoid(gz + az + bz);
        float n = fast_tanh(gn + r * (an + bn));
        float hnew = (1.f - z) * n + z * hprev;

        if (l == 0) {
            stcg_f32(&d_hbuf[(t + 1) & 1][j], hnew);   // publish state t+1 to L2
            d_hs[(size_t)t * HD + j] = hnew;           // history for attention
        }
        hprev = hnew;
        gr = gr2; gz = gz2; gn = gn2;

        // --- publish this block's epoch ---
        __syncthreads();
        if (tid == 0) {
            __threadfence();
            st_rel(&d_done[blockIdx.x], (unsigned)(t + 1));
        }
        // no trailing sync needed: warps independently re-poll next iteration
    }
}

// ============================================================
// attention: logits, softmax, deterministic 2-stage weighted sum
// ============================================================
__global__ __launch_bounds__(256) void att_logits_kernel(const float* __restrict__ watt) {
    const int t = blockIdx.x * 8 + (threadIdx.x >> 5);
    const int l = threadIdx.x & 31;
    const float* hp = d_hs + (size_t)t * HD;
    float acc = 0.f;
#pragma unroll
    for (int q = 0; q < 4; q++) {
        const int c = 4 * (l + 32 * q);
        float4 h = *(const float4*)(hp + c);
        float4 wv = *(const float4*)(watt + c);
        acc = fmaf(h.x, wv.x, fmaf(h.y, wv.y, fmaf(h.z, wv.z, fmaf(h.w, wv.w, acc))));
    }
#pragma unroll
    for (int off = 16; off; off >>= 1) acc += __shfl_xor_sync(0xffffffffu, acc, off);
    if (l == 0) d_logits[t] = acc;
}

__global__ __launch_bounds__(1024) void att_softmax_kernel() {
    __shared__ float sh[32];
    const int tid = threadIdx.x;
    const int l = tid & 31, w = tid >> 5;

    float m = -1e30f;
    for (int i = tid; i < T_STEPS; i += 1024) m = fmaxf(m, d_logits[i]);
#pragma unroll
    for (int off = 16; off; off >>= 1) m = fmaxf(m, __shfl_xor_sync(0xffffffffu, m, off));
    if (l == 0) sh[w] = m;
    __syncthreads();
    if (tid < 32) {
        float v = sh[tid];
#pragma unroll
        for (int off = 16; off; off >>= 1) v = fmaxf(v, __shfl_xor_sync(0xffffffffu, v, off));
        if (tid == 0) sh[0] = v;
    }
    __syncthreads();
    const float mall = sh[0];
    __syncthreads();

    float s = 0.f;
    for (int i = tid; i < T_STEPS; i += 1024) s += __expf(d_logits[i] - mall);
#pragma unroll
    for (int off = 16; off; off >>= 1) s += __shfl_xor_sync(0xffffffffu, s, off);
    if (l == 0) sh[w] = s;
    __syncthreads();
    if (tid < 32) {
        float v = sh[tid];
#pragma unroll
        for (int off = 16; off; off >>= 1) v += __shfl_xor_sync(0xffffffffu, v, off);
        if (tid == 0) sh[0] = v;
    }
    __syncthreads();
    const float inv = __fdividef(1.f, sh[0]);
    for (int i = tid; i < T_STEPS; i += 1024) d_alpha[i] = __expf(d_logits[i] - mall) * inv;
}

__global__ __launch_bounds__(512) void att_part_kernel() {
    const int d = threadIdx.x;
    const int b = blockIdx.x;
    float acc = 0.f;
    const int tbeg = b * (T_STEPS / NBP);
    for (int t = tbeg; t < tbeg + (T_STEPS / NBP); t++)
        acc = fmaf(d_alpha[t], d_hs[(size_t)t * HD + d], acc);
    d_part[b * HD + d] = acc;
}

__global__ __launch_bounds__(512) void att_final_kernel(float* __restrict__ out) {
    const int d = threadIdx.x;
    float acc = 0.f;
#pragma unroll 4
    for (int b = 0; b < NBP; b++) acc += d_part[b * HD + d];
    out[d] = acc;
}

// ============================================================
extern "C" void kernel_launch(void* const* d_in, const int* in_sizes, int n_in,
                              void* d_out, int out_size) {
    const float* Hm   = (const float*)d_in[0];
    // d_in[1] = TE (unused by reference)
    const float* Xe   = (const float*)d_in[2];
    const float* Wih  = (const float*)d_in[3];
    const float* Whh  = (const float*)d_in[4];
    const float* bih  = (const float*)d_in[5];
    const float* bhh  = (const float*)d_in[6];
    const float* watt = (const float*)d_in[7];
    float* out = (float*)d_out;

    gemm1_kernel<<<dim3(T_STEPS / 128, VD / 128), 256>>>(Hm, Xe);
    gemm2_kernel<<<dim3(T_STEPS / 128, G3 / 128), 256>>>(Wih, bih);
    init_kernel<<<1, 512>>>();
    gru_scan_kernel<<<NB, 256>>>(Whh, bhh);
    att_logits_kernel<<<T_STEPS / 8, 256>>>(watt);
    att_softmax_kernel<<<1, 1024>>>();
    att_part_kernel<<<NBP, 512>>>();
    att_final_kernel<<<1, 512>>>(out);
}